// round 2
// baseline (speedup 1.0000x reference)
#include <cuda_runtime.h>
#include <cstdint>

#define BB 64
#define NN 500
#define CC 128
#define HH 256

// scratch activations for the MLP (ping-pong)
__device__ float g_act[2][BB * HH];

// ---------------------------------------------------------------------------
// Correlation kernel: grid (2, B); blockIdx.x = channel half, blockIdx.y = b
// 1024 threads. smem: px/py/pz/s (4*500) + data slice (500*65) + corr(64) + cnt
// ---------------------------------------------------------------------------
#define CORR_SMEM ((4 * NN + NN * 65 + 64 + 4) * 4 + 16)

__global__ void corr_kernel(const float* __restrict__ xyz,   // [B,3,N]
                            const float* __restrict__ pts,   // [B,C,N]
                            float* __restrict__ corr_out)    // [B,C]
{
    extern __shared__ float sm[];
    float* px    = sm;                 // N
    float* py    = px + NN;            // N
    float* pz    = py + NN;            // N
    float* ss    = pz + NN;            // N
    float* dataS = ss + NN;            // N * 65  (64 channels + pad)
    float* corrS = dataS + NN * 65;    // 64
    int*   cntS  = (int*)(corrS + 64);

    const int b    = blockIdx.y;
    const int half = blockIdx.x;       // channel half: 0 -> ch 0..63, 1 -> 64..127
    const int tid  = threadIdx.x;

    if (tid < 64) corrS[tid] = 0.0f;
    if (tid == 0) *cntS = 0;

    // load xyz (coalesced) and compute s
    const float* xb = xyz + (size_t)b * 3 * NN;
    for (int i = tid; i < NN; i += blockDim.x) {
        float x = xb[i];
        float y = xb[NN + i];
        float z = xb[2 * NN + i];
        px[i] = x; py[i] = y; pz[i] = z;
        ss[i] = x * x + y * y + z * z;
    }

    // load 64-channel data slice, transposed: dataS[j*65 + c] = pts[b, half*64+c, j]
    const float* pb = pts + (size_t)b * CC * NN + (size_t)half * 64 * NN;
    for (int idx = tid; idx < 64 * NN; idx += blockDim.x) {
        int c = idx / NN;
        int j = idx - c * NN;
        dataS[j * 65 + c] = pb[c * NN + j];   // read coalesced over j
    }
    __syncthreads();

    const int warp = tid >> 5;
    const int lane = tid & 31;
    float corr0 = 0.0f, corr1 = 0.0f;
    int   cnt   = 0;

    for (int i = warp; i < NN; i += 32) {
        const float xi = px[i], yi = py[i], zi = pz[i], si = ss[i];
        const float di0 = dataS[i * 65 + lane];
        const float di1 = dataS[i * 65 + 32 + lane];
        float t0 = 0.0f, t1 = 0.0f;

        for (int jb = 0; jb < NN; jb += 32) {
            const int j = jb + lane;
            bool pred = false;
            if (j < NN) {
                float dot = xi * px[j] + yi * py[j] + zi * pz[j];
                float sq  = si + ss[j] - 2.0f * dot;
                float d   = sqrtf(fabsf(sq));
                pred = (d > 0.19f) && (d < 0.21f);
            }
            unsigned m = __ballot_sync(0xffffffffu, pred);
            cnt += __popc(m);
            while (m) {
                int jj = jb + (__ffs(m) - 1);
                m &= m - 1;
                t0 += dataS[jj * 65 + lane];
                t1 += dataS[jj * 65 + 32 + lane];
            }
        }
        corr0 += t0 * di0;
        corr1 += t1 * di1;
    }

    atomicAdd(&corrS[lane],      corr0);
    atomicAdd(&corrS[32 + lane], corr1);
    if (lane == 0) atomicAdd(cntS, cnt);
    __syncthreads();

    if (tid < 64) {
        float cf = fmaxf((float)(*cntS), 1.0f);
        corr_out[b * CC + half * 64 + tid] = corrS[tid] / cf;
    }
}

// ---------------------------------------------------------------------------
// One BN-MLP layer: out = relu(BN(x @ W^T + bias))
// grid = 8 blocks (32 output cols each), 256 threads (8 warps x 32 lanes)
// warp = n-group, lane = output column within block's slice
// ---------------------------------------------------------------------------
#define MLP_SMEM ((BB * HH + 32 * 257 + 256 + 256 + 32 + 32) * 4)

__global__ void mlp_layer(const float* __restrict__ x0,
                          const float* __restrict__ x1, int split,
                          const float* __restrict__ W,
                          const float* __restrict__ bias,
                          const float* __restrict__ gam,
                          const float* __restrict__ bet,
                          float* __restrict__ out)
{
    extern __shared__ float sm[];
    float* xs   = sm;                  // 64*256
    float* ws   = xs + BB * HH;        // 32*257 (padded)
    float* redS = ws + 32 * 257;       // 256
    float* redQ = redS + 256;          // 256
    float* mS   = redQ + 256;          // 32
    float* iS   = mS + 32;             // 32

    const int tid   = threadIdx.x;     // 256
    const int obase = blockIdx.x * 32;

    for (int idx = tid; idx < BB * HH; idx += 256) {
        int n = idx >> 8, k = idx & 255;
        float v;
        if (split) v = (k < 128) ? x0[n * 128 + k] : x1[n * 128 + (k - 128)];
        else       v = x0[idx];
        xs[idx] = v;
    }
    for (int idx = tid; idx < 32 * HH; idx += 256) {
        int oo = idx >> 8, k = idx & 255;
        ws[oo * 257 + k] = W[(size_t)(obase + oo) * HH + k];
    }
    __syncthreads();

    const int warp = tid >> 5;
    const int lane = tid & 31;
    const int o    = obase + lane;

    float acc[8] = {0, 0, 0, 0, 0, 0, 0, 0};
    for (int k = 0; k < HH; k++) {
        float wv = ws[lane * 257 + k];       // conflict-free (stride 257)
        #pragma unroll
        for (int r = 0; r < 8; r++)
            acc[r] = fmaf(xs[(warp + 8 * r) * HH + k], wv, acc[r]);  // broadcast
    }

    const float bi = bias[o];
    float ps = 0.0f, pq = 0.0f;
    #pragma unroll
    for (int r = 0; r < 8; r++) {
        acc[r] += bi;
        ps += acc[r];
        pq += acc[r] * acc[r];
    }
    redS[tid] = ps;
    redQ[tid] = pq;
    __syncthreads();

    if (tid < 32) {
        float s = 0.0f, q = 0.0f;
        #pragma unroll
        for (int w = 0; w < 8; w++) { s += redS[w * 32 + tid]; q += redQ[w * 32 + tid]; }
        float m = s * (1.0f / 64.0f);
        float v = q * (1.0f / 64.0f) - m * m;   // biased variance
        mS[tid] = m;
        iS[tid] = rsqrtf(v + 1e-5f);
    }
    __syncthreads();

    const float m = mS[lane], iv = iS[lane];
    const float gl = gam[o], bl = bet[o];
    #pragma unroll
    for (int r = 0; r < 8; r++) {
        float hv = gl * (acc[r] - m) * iv + bl;
        out[(warp + 8 * r) * HH + o] = fmaxf(hv, 0.0f);
    }
}

// ---------------------------------------------------------------------------
// Final linear: tc[b] = h[b,:] . w4 + b4   (1 block, 256 threads)
// ---------------------------------------------------------------------------
__global__ void fc_final(const float* __restrict__ h,
                         const float* __restrict__ w4,
                         const float* __restrict__ b4,
                         float* __restrict__ tc)
{
    const int tid  = threadIdx.x;
    const int warp = tid >> 5, lane = tid & 31;
    for (int bi = warp; bi < BB; bi += 8) {
        float p = 0.0f;
        for (int k = lane; k < HH; k += 32) p += h[bi * HH + k] * w4[k];
        #pragma unroll
        for (int off = 16; off; off >>= 1) p += __shfl_down_sync(0xffffffffu, p, off);
        if (lane == 0) tc[bi] = p + b4[0];
    }
}

// ---------------------------------------------------------------------------
// tsys[b] = mean over N of temp[b,0,:]   (1 block, 1024 threads)
// ---------------------------------------------------------------------------
__global__ void tsys_kernel(const float* __restrict__ temp, float* __restrict__ tsys)
{
    const int tid  = threadIdx.x;
    const int warp = tid >> 5, lane = tid & 31;
    for (int bi = warp; bi < BB; bi += 32) {
        float s = 0.0f;
        for (int j = lane; j < NN; j += 32) s += temp[bi * NN + j];
        #pragma unroll
        for (int off = 16; off; off >>= 1) s += __shfl_down_sync(0xffffffffu, s, off);
        if (lane == 0) tsys[bi] = s * (1.0f / (float)NN);
    }
}

// ---------------------------------------------------------------------------
extern "C" void kernel_launch(void* const* d_in, const int* in_sizes, int n_in,
                              void* d_out, int out_size)
{
    const float* xyz  = (const float*)d_in[0];   // [64,3,500]
    const float* pts  = (const float*)d_in[1];   // [64,128,500]
    const float* l3   = (const float*)d_in[2];   // [64,128]
    const float* temp = (const float*)d_in[3];   // [64,1,500]
    const float* w0   = (const float*)d_in[4];
    const float* b0   = (const float*)d_in[5];
    const float* g0   = (const float*)d_in[6];
    const float* bb0  = (const float*)d_in[7];
    const float* w1   = (const float*)d_in[8];
    const float* b1   = (const float*)d_in[9];
    const float* g1   = (const float*)d_in[10];
    const float* bb1  = (const float*)d_in[11];
    const float* w2   = (const float*)d_in[12];
    const float* b2   = (const float*)d_in[13];
    const float* g2   = (const float*)d_in[14];
    const float* bb2  = (const float*)d_in[15];
    const float* w3   = (const float*)d_in[16];  // fc_lt1
    const float* b3   = (const float*)d_in[17];
    const float* g3   = (const float*)d_in[18];
    const float* bb3  = (const float*)d_in[19];
    const float* w4   = (const float*)d_in[20];  // fc_lt4 [1,256]
    const float* b4   = (const float*)d_in[21];

    float* out   = (float*)d_out;
    float* tc    = out;                                   // [64]
    float* tsys  = out + 64;                              // [64]
    float* opts  = out + 128;                             // [64,128,500]
    float* ocorr = out + 128 + (size_t)BB * CC * NN;      // [64,128]

    cudaFuncSetAttribute(corr_kernel, cudaFuncAttributeMaxDynamicSharedMemorySize, CORR_SMEM);
    cudaFuncSetAttribute(mlp_layer,   cudaFuncAttributeMaxDynamicSharedMemorySize, MLP_SMEM);

    float* act0 = nullptr;
    cudaGetSymbolAddress((void**)&act0, g_act);
    float* act1 = act0 + BB * HH;

    // independent passthrough outputs
    tsys_kernel<<<1, 1024>>>(temp, tsys);
    cudaMemcpyAsync(opts, pts, (size_t)BB * CC * NN * sizeof(float),
                    cudaMemcpyDeviceToDevice);

    // correlation
    corr_kernel<<<dim3(2, BB), 1024, CORR_SMEM>>>(xyz, pts, ocorr);

    // MLP
    mlp_layer<<<8, 256, MLP_SMEM>>>(ocorr, l3, 1, w0, b0, g0, bb0, act0);
    mlp_layer<<<8, 256, MLP_SMEM>>>(act0, nullptr, 0, w1, b1, g1, bb1, act1);
    mlp_layer<<<8, 256, MLP_SMEM>>>(act1, nullptr, 0, w2, b2, g2, bb2, act0);
    mlp_layer<<<8, 256, MLP_SMEM>>>(act0, nullptr, 0, w3, b3, g3, bb3, act1);
    fc_final<<<1, 256>>>(act1, w4, b4, tc);

    (void)in_sizes; (void)n_in; (void)out_size;
}

// round 4
// speedup vs baseline: 1.2715x; 1.2715x over previous
#include <cuda_runtime.h>
#include <cstdint>

#define BB 64
#define NN 500
#define CC 128
#define HH 256
#define GRIDN 128
#define THREADS 1024
#define XS_STRIDE 264   // 256 + 8 pad: 1056B row stride, kills LDS.128 bank conflicts

// MLP activation ping-pong + grid-barrier state
__device__ __align__(16) float g_act[2][BB * HH];
__device__ unsigned g_count[8];
__device__ volatile unsigned g_sense[8];

// Sense-reversing grid barrier. Self-resetting across graph replays.
// __threadfence() by every thread: publishes this thread's global writes AND
// (gpu scope -> CCTL.IVALL) invalidates L1D so post-barrier reads hit fresh L2.
__device__ __forceinline__ void grid_barrier(int idx)
{
    __threadfence();
    __syncthreads();
    if (threadIdx.x == 0) {
        unsigned s = g_sense[idx];
        unsigned arrived = atomicAdd(&g_count[idx], 1u);
        if (arrived == GRIDN - 1u) {
            g_count[idx] = 0u;
            __threadfence();
            g_sense[idx] = s + 1u;
        } else {
            while (g_sense[idx] == s) { }
        }
    }
    __syncthreads();
}

// smem (dynamic, aliased between phases):
// Phase A: px/py/pz/ss (4*500) | dataS 500*65 | corrS 64 | cnt
// Phase B: xs 64*264 | ws 2*264 | dotS 128 | mS 2 | iS 2
#define SMEM_FLOATS (4 * NN + NN * 65 + 64 + 8)
#define SMEM_BYTES  (SMEM_FLOATS * 4)

__global__ __launch_bounds__(THREADS, 1)
void mega_kernel(const float* __restrict__ xyz,   // [B,3,N]
                 const float* __restrict__ pts,   // [B,C,N]
                 const float* __restrict__ l3,    // [B,C]
                 const float* __restrict__ temp,  // [B,1,N]
                 const float* __restrict__ w0, const float* __restrict__ b0,
                 const float* __restrict__ g0, const float* __restrict__ e0,
                 const float* __restrict__ w1, const float* __restrict__ b1,
                 const float* __restrict__ g1, const float* __restrict__ e1,
                 const float* __restrict__ w2, const float* __restrict__ b2,
                 const float* __restrict__ g2, const float* __restrict__ e2,
                 const float* __restrict__ w3, const float* __restrict__ b3,
                 const float* __restrict__ g3, const float* __restrict__ e3,
                 const float* __restrict__ w4, const float* __restrict__ b4,
                 float* __restrict__ tc,          // out[0:64]
                 float* __restrict__ tsys,        // out[64:128]
                 float* __restrict__ opts,        // out[128 : 128+B*C*N]
                 float* __restrict__ ocorr)       // out[... : +B*C]
{
    extern __shared__ float sm[];
    const int tid  = threadIdx.x;
    const int bid  = blockIdx.x;
    const int warp = tid >> 5;
    const int lane = tid & 31;

    const int b    = bid >> 1;
    const int half = bid & 1;

    // ------------------------------------------------------------------
    // Phase A0: tsys (odd blocks) — uses sm[0..31] before corr loads
    // ------------------------------------------------------------------
    if (half == 1) {
        float s = (tid < NN) ? temp[b * NN + tid] : 0.0f;
        #pragma unroll
        for (int off = 16; off; off >>= 1) s += __shfl_down_sync(0xffffffffu, s, off);
        if (lane == 0) sm[warp] = s;
        __syncthreads();
        if (tid < 32) {
            float v = (tid < 16) ? sm[tid] : 0.0f;
            #pragma unroll
            for (int off = 8; off; off >>= 1) v += __shfl_down_sync(0xffffffffu, v, off);
            if (tid == 0) tsys[b] = v * (1.0f / (float)NN);
        }
        __syncthreads();
    }

    // ------------------------------------------------------------------
    // Phase A1: l2_points passthrough copy (all blocks, float4)
    // ------------------------------------------------------------------
    {
        const float4* s4 = (const float4*)pts;
        float4*       d4 = (float4*)opts;
        const int total4 = (BB * CC * NN) / 4;  // 1,024,000
        #pragma unroll 2
        for (int i = bid * THREADS + tid; i < total4; i += GRIDN * THREADS)
            d4[i] = s4[i];
    }

    // ------------------------------------------------------------------
    // Phase A2: correlation (block owns (b, channel-half))
    // ------------------------------------------------------------------
    {
        float* px    = sm;
        float* py    = px + NN;
        float* pz    = py + NN;
        float* ss    = pz + NN;
        float* dataS = ss + NN;              // NN * 65
        float* corrS = dataS + NN * 65;      // 64
        int*   cntS  = (int*)(corrS + 64);

        if (tid < 64) corrS[tid] = 0.0f;
        if (tid == 64) *cntS = 0;

        const float* xb = xyz + (size_t)b * 3 * NN;
        for (int i = tid; i < NN; i += THREADS) {
            float x = xb[i];
            float y = xb[NN + i];
            float z = xb[2 * NN + i];
            px[i] = x; py[i] = y; pz[i] = z;
            ss[i] = x * x + y * y + z * z;
        }

        const float* pb = pts + (size_t)b * CC * NN + (size_t)half * 64 * NN;
        for (int idx = tid; idx < 64 * NN; idx += THREADS) {
            int c = idx / NN;
            int j = idx - c * NN;
            dataS[j * 65 + c] = pb[c * NN + j];
        }
        __syncthreads();

        float corr0 = 0.0f, corr1 = 0.0f;
        int   cnt   = 0;

        for (int i = warp; i < NN; i += 32) {
            const float xi = px[i], yi = py[i], zi = pz[i], si = ss[i];
            const float di0 = dataS[i * 65 + lane];
            const float di1 = dataS[i * 65 + 32 + lane];
            float t0 = 0.0f, t1 = 0.0f;

            for (int jb = 0; jb < NN; jb += 32) {
                const int j = jb + lane;
                bool pred = false;
                if (j < NN) {
                    float dot = xi * px[j] + yi * py[j] + zi * pz[j];
                    float sq  = si + ss[j] - 2.0f * dot;
                    float d   = sqrtf(fabsf(sq));
                    pred = (d > 0.19f) && (d < 0.21f);
                }
                unsigned m = __ballot_sync(0xffffffffu, pred);
                cnt += __popc(m);
                while (m) {
                    int jj = jb + (__ffs(m) - 1);
                    m &= m - 1;
                    t0 += dataS[jj * 65 + lane];
                    t1 += dataS[jj * 65 + 32 + lane];
                }
            }
            corr0 += t0 * di0;
            corr1 += t1 * di1;
        }

        atomicAdd(&corrS[lane],      corr0);
        atomicAdd(&corrS[32 + lane], corr1);
        if (lane == 0) atomicAdd(cntS, cnt);
        __syncthreads();

        if (tid < 64) {
            float cf = fmaxf((float)(*cntS), 1.0f);
            ocorr[b * CC + half * 64 + tid] = corrS[tid] / cf;
        }
    }

    grid_barrier(0);

    // ------------------------------------------------------------------
    // Phase B: 4 BN-MLP layers. Each block owns 2 output columns.
    // ------------------------------------------------------------------
    {
        float* xs   = sm;                       // 64 * XS_STRIDE
        float* ws   = xs + BB * XS_STRIDE;      // 2 * XS_STRIDE
        float* dotS = ws + 2 * XS_STRIDE;       // 128
        float* mS   = dotS + 128;               // 2
        float* iS   = mS + 2;                   // 2

        const float* Wl[4] = {w0, w1, w2, w3};
        const float* Bl[4] = {b0, b1, b2, b3};
        const float* Gl[4] = {g0, g1, g2, g3};
        const float* El[4] = {e0, e1, e2, e3};

        const int o0 = bid * 2;

        for (int l = 0; l < 4; l++) {
            // --- load x [64,256] into smem (padded stride), float4 ---
            if (l == 0) {
                const float4* c4p = (const float4*)ocorr;  // [B,128]
                const float4* l4p = (const float4*)l3;     // [B,128]
                for (int i = tid; i < BB * 64; i += THREADS) {
                    int n = i >> 6, c4 = i & 63;
                    float4 v = (c4 < 32) ? __ldcg(c4p + n * 32 + c4)
                                         : __ldcg(l4p + n * 32 + (c4 - 32));
                    *(float4*)&xs[n * XS_STRIDE + c4 * 4] = v;
                }
            } else {
                const float4* src = (const float4*)&g_act[(l + 1) & 1][0]; // prev dst
                for (int i = tid; i < BB * 64; i += THREADS) {
                    int n = i >> 6, c4 = i & 63;
                    *(float4*)&xs[n * XS_STRIDE + c4 * 4] = __ldcg(src + i);
                }
            }
            // --- load this block's 2 weight rows ---
            if (tid < 2 * HH) {
                int oo = tid >> 8, k = tid & 255;
                ws[oo * XS_STRIDE + k] = Wl[l][(size_t)(o0 + oo) * HH + k];
            }
            __syncthreads();

            // --- dots: 128 outputs x 8 threads each ---
            const int sub  = tid & 7;
            const int outi = tid >> 3;          // 0..127
            const int n    = outi >> 1;
            const int oc   = outi & 1;
            {
                const float* xr = &xs[n * XS_STRIDE + sub * 4];
                const float* wr = &ws[oc * XS_STRIDE + sub * 4];
                float p = 0.0f;
                #pragma unroll
                for (int t = 0; t < 8; t++) {
                    float4 xv = *(const float4*)(xr + t * 32);
                    float4 wv = *(const float4*)(wr + t * 32);
                    p = fmaf(xv.x, wv.x, p);
                    p = fmaf(xv.y, wv.y, p);
                    p = fmaf(xv.z, wv.z, p);
                    p = fmaf(xv.w, wv.w, p);
                }
                p += __shfl_down_sync(0xffffffffu, p, 4, 8);
                p += __shfl_down_sync(0xffffffffu, p, 2, 8);
                p += __shfl_down_sync(0xffffffffu, p, 1, 8);
                if (sub == 0) dotS[outi] = p + Bl[l][o0 + oc];
            }
            __syncthreads();

            // --- BN stats per column (warp 0 -> oc0, warp 1 -> oc1) ---
            if (tid < 64) {
                int oc2 = tid >> 5;
                int ll  = tid & 31;
                float a = dotS[ll * 2 + oc2];
                float c = dotS[(ll + 32) * 2 + oc2];
                float s = a + c, q = a * a + c * c;
                #pragma unroll
                for (int off = 16; off; off >>= 1) {
                    s += __shfl_down_sync(0xffffffffu, s, off);
                    q += __shfl_down_sync(0xffffffffu, q, off);
                }
                if (ll == 0) {
                    float m = s * (1.0f / 64.0f);
                    float v = q * (1.0f / 64.0f) - m * m;
                    mS[oc2] = m;
                    iS[oc2] = rsqrtf(v + 1e-5f);
                }
            }
            __syncthreads();

            // --- BN + relu, write to ping-pong ---
            if (tid < 128) {
                int nn = tid >> 1, occ = tid & 1;
                int o  = o0 + occ;
                float d = dotS[tid];
                float h = Gl[l][o] * (d - mS[occ]) * iS[occ] + El[l][o];
                g_act[l & 1][nn * HH + o] = fmaxf(h, 0.0f);
            }

            grid_barrier(1 + l);
        }
    }

    // ------------------------------------------------------------------
    // Final FC (block 0): tc[n] = h[n,:] . w4 + b4, h = g_act[1]
    // ------------------------------------------------------------------
    if (bid == 0) {
        const int n   = tid >> 4;   // 64
        const int sub = tid & 15;   // 16
        const float* hr = &g_act[1][n * HH + sub * 16];
        float p = 0.0f;
        #pragma unroll
        for (int t = 0; t < 16; t++)
            p = fmaf(__ldcg(hr + t), w4[sub * 16 + t], p);
        p += __shfl_down_sync(0xffffffffu, p, 8, 16);
        p += __shfl_down_sync(0xffffffffu, p, 4, 16);
        p += __shfl_down_sync(0xffffffffu, p, 2, 16);
        p += __shfl_down_sync(0xffffffffu, p, 1, 16);
        if (sub == 0) tc[n] = p + b4[0];
    }
}

// ---------------------------------------------------------------------------
extern "C" void kernel_launch(void* const* d_in, const int* in_sizes, int n_in,
                              void* d_out, int out_size)
{
    const float* xyz  = (const float*)d_in[0];
    const float* pts  = (const float*)d_in[1];
    const float* l3   = (const float*)d_in[2];
    const float* temp = (const float*)d_in[3];
    const float* w0   = (const float*)d_in[4];
    const float* b0   = (const float*)d_in[5];
    const float* g0   = (const float*)d_in[6];
    const float* e0   = (const float*)d_in[7];
    const float* w1   = (const float*)d_in[8];
    const float* b1   = (const float*)d_in[9];
    const float* g1   = (const float*)d_in[10];
    const float* e1   = (const float*)d_in[11];
    const float* w2   = (const float*)d_in[12];
    const float* b2   = (const float*)d_in[13];
    const float* g2   = (const float*)d_in[14];
    const float* e2   = (const float*)d_in[15];
    const float* w3   = (const float*)d_in[16];
    const float* b3   = (const float*)d_in[17];
    const float* g3   = (const float*)d_in[18];
    const float* e3   = (const float*)d_in[19];
    const float* w4   = (const float*)d_in[20];
    const float* b4   = (const float*)d_in[21];

    float* out   = (float*)d_out;
    float* tc    = out;
    float* tsys  = out + 64;
    float* opts  = out + 128;
    float* ocorr = out + 128 + (size_t)BB * CC * NN;

    cudaFuncSetAttribute(mega_kernel, cudaFuncAttributeMaxDynamicSharedMemorySize,
                         SMEM_BYTES);

    mega_kernel<<<GRIDN, THREADS, SMEM_BYTES>>>(
        xyz, pts, l3, temp,
        w0, b0, g0, e0,
        w1, b1, g1, e1,
        w2, b2, g2, e2,
        w3, b3, g3, e3,
        w4, b4,
        tc, tsys, opts, ocorr);

    (void)in_sizes; (void)n_in; (void)out_size;
}

// round 5
// speedup vs baseline: 1.9966x; 1.5703x over previous
#include <cuda_runtime.h>
#include <cstdint>

#define BB 64
#define NN 500
#define CC 128
#define HH 256
#define GRIDN 128
#define THREADS 1024
#define XS_STRIDE 264   // 256 + 8 pad

// band thresholds squared (0.19^2, 0.21^2)
#define LO2 0.0361f
#define HI2 0.0441f

// MLP activation ping-pong + grid-barrier state
__device__ __align__(16) float g_act[2][BB * HH];
__device__ unsigned g_count[8];
__device__ volatile unsigned g_sense[8];

__device__ __forceinline__ void grid_barrier(int idx)
{
    __threadfence();
    __syncthreads();
    if (threadIdx.x == 0) {
        unsigned s = g_sense[idx];
        unsigned arrived = atomicAdd(&g_count[idx], 1u);
        if (arrived == GRIDN - 1u) {
            g_count[idx] = 0u;
            __threadfence();
            g_sense[idx] = s + 1u;
        } else {
            while (g_sense[idx] == s) { }
        }
    }
    __syncthreads();
}

// smem (dynamic, aliased between phases):
// Phase A: pj4 (500 float4) | dataS 500*65 | corrS 64 | cnt
// Phase B: xs 64*264 | ws 2*264 | dotS 128 | mS 2 | iS 2
#define SMEM_FLOATS (4 * NN + NN * 65 + 64 + 8)
#define SMEM_BYTES  (SMEM_FLOATS * 4)

__global__ __launch_bounds__(THREADS, 1)
void mega_kernel(const float* __restrict__ xyz,   // [B,3,N]
                 const float* __restrict__ pts,   // [B,C,N]
                 const float* __restrict__ l3,    // [B,C]
                 const float* __restrict__ temp,  // [B,1,N]
                 const float* __restrict__ w0, const float* __restrict__ b0,
                 const float* __restrict__ g0, const float* __restrict__ e0,
                 const float* __restrict__ w1, const float* __restrict__ b1,
                 const float* __restrict__ g1, const float* __restrict__ e1,
                 const float* __restrict__ w2, const float* __restrict__ b2,
                 const float* __restrict__ g2, const float* __restrict__ e2,
                 const float* __restrict__ w3, const float* __restrict__ b3,
                 const float* __restrict__ g3, const float* __restrict__ e3,
                 const float* __restrict__ w4, const float* __restrict__ b4,
                 float* __restrict__ tc,
                 float* __restrict__ tsys,
                 float* __restrict__ opts,
                 float* __restrict__ ocorr)
{
    extern __shared__ float sm[];
    const int tid  = threadIdx.x;
    const int bid  = blockIdx.x;
    const int warp = tid >> 5;
    const int lane = tid & 31;

    const int b    = bid >> 1;
    const int half = bid & 1;

    // ------------------------------------------------------------------
    // Phase A0: tsys (odd blocks)
    // ------------------------------------------------------------------
    if (half == 1) {
        float s = (tid < NN) ? temp[b * NN + tid] : 0.0f;
        #pragma unroll
        for (int off = 16; off; off >>= 1) s += __shfl_down_sync(0xffffffffu, s, off);
        if (lane == 0) sm[warp] = s;
        __syncthreads();
        if (tid < 32) {
            float v = (tid < 16) ? sm[tid] : 0.0f;
            #pragma unroll
            for (int off = 8; off; off >>= 1) v += __shfl_down_sync(0xffffffffu, v, off);
            if (tid == 0) tsys[b] = v * (1.0f / (float)NN);
        }
        __syncthreads();
    }

    // ------------------------------------------------------------------
    // Phase A1: l2_points passthrough copy (all blocks, float4)
    // ------------------------------------------------------------------
    {
        const float4* s4 = (const float4*)pts;
        float4*       d4 = (float4*)opts;
        const int total4 = (BB * CC * NN) / 4;
        #pragma unroll 2
        for (int i = bid * THREADS + tid; i < total4; i += GRIDN * THREADS)
            d4[i] = s4[i];
    }

    // ------------------------------------------------------------------
    // Phase A2: correlation. Upper-triangle scan (j > i), squared-band
    // predicate (no sqrt), float4-packed point records.
    // corr_c = S_upper / max(cnt_upper,1)  ==  S_full / max(cnt_full,1)
    // ------------------------------------------------------------------
    {
        float4* pj4   = (float4*)sm;           // 500 x {x,y,z,s}
        float*  dataS = sm + 4 * NN;           // NN * 65
        float*  corrS = dataS + NN * 65;       // 64
        int*    cntS  = (int*)(corrS + 64);

        if (tid < 64) corrS[tid] = 0.0f;
        if (tid == 64) *cntS = 0;

        const float* xb = xyz + (size_t)b * 3 * NN;
        for (int i = tid; i < NN; i += THREADS) {
            float x = xb[i];
            float y = xb[NN + i];
            float z = xb[2 * NN + i];
            pj4[i] = make_float4(x, y, z, x * x + y * y + z * z);
        }

        const float* pb = pts + (size_t)b * CC * NN + (size_t)half * 64 * NN;
        for (int idx = tid; idx < 64 * NN; idx += THREADS) {
            int c = idx / NN;
            int j = idx - c * NN;
            dataS[j * 65 + c] = pb[c * NN + j];
        }
        __syncthreads();

        float corr0 = 0.0f, corr1 = 0.0f;
        int   cnt   = 0;

        for (int i = warp; i < NN; i += 32) {
            const float4 pi = pj4[i];
            const float di0 = dataS[i * 65 + lane];
            const float di1 = dataS[i * 65 + 32 + lane];
            float t0 = 0.0f, t1 = 0.0f;

            const int jb0 = i & ~31;   // 32-aligned block containing i

            // diagonal block: j in [jb0, jb0+32), need j > i (and j < NN when jb0==480)
            {
                const int j = jb0 + lane;
                bool pred = false;
                if (j > i && j < NN) {
                    float4 pj = pj4[j];
                    float dot = pi.x * pj.x + pi.y * pj.y + pi.z * pj.z;
                    float sq  = fabsf(pi.w + pj.w - 2.0f * dot);
                    pred = (sq > LO2) && (sq < HI2);
                }
                unsigned m = __ballot_sync(0xffffffffu, pred);
                cnt += __popc(m);
                while (m) {
                    int jj = jb0 + (__ffs(m) - 1);
                    m &= m - 1;
                    t0 += dataS[jj * 65 + lane];
                    t1 += dataS[jj * 65 + 32 + lane];
                }
            }

            // full blocks: jb in (jb0, 480), all j > i and j < NN
            #pragma unroll 2
            for (int jb = jb0 + 32; jb < 480; jb += 32) {
                float4 pj = pj4[jb + lane];
                float dot = pi.x * pj.x + pi.y * pj.y + pi.z * pj.z;
                float sq  = fabsf(pi.w + pj.w - 2.0f * dot);
                bool pred = (sq > LO2) && (sq < HI2);
                unsigned m = __ballot_sync(0xffffffffu, pred);
                cnt += __popc(m);
                while (m) {
                    int jj = jb + (__ffs(m) - 1);
                    m &= m - 1;
                    t0 += dataS[jj * 65 + lane];
                    t1 += dataS[jj * 65 + 32 + lane];
                }
            }

            // tail block jb=480 (j in [480,500)), only when not already the diagonal
            if (jb0 < 480) {
                const int j = 480 + lane;
                bool pred = false;
                if (j < NN) {
                    float4 pj = pj4[j];
                    float dot = pi.x * pj.x + pi.y * pj.y + pi.z * pj.z;
                    float sq  = fabsf(pi.w + pj.w - 2.0f * dot);
                    pred = (sq > LO2) && (sq < HI2);
                }
                unsigned m = __ballot_sync(0xffffffffu, pred);
                cnt += __popc(m);
                while (m) {
                    int jj = 480 + (__ffs(m) - 1);
                    m &= m - 1;
                    t0 += dataS[jj * 65 + lane];
                    t1 += dataS[jj * 65 + 32 + lane];
                }
            }

            corr0 += t0 * di0;
            corr1 += t1 * di1;
        }

        atomicAdd(&corrS[lane],      corr0);
        atomicAdd(&corrS[32 + lane], corr1);
        if (lane == 0) atomicAdd(cntS, cnt);
        __syncthreads();

        if (tid < 64) {
            float cf = fmaxf((float)(*cntS), 1.0f);
            ocorr[b * CC + half * 64 + tid] = corrS[tid] / cf;
        }
    }

    grid_barrier(0);

    // ------------------------------------------------------------------
    // Phase B: 4 BN-MLP layers. Each block owns 2 output columns.
    // ------------------------------------------------------------------
    {
        float* xs   = sm;                       // 64 * XS_STRIDE
        float* ws   = xs + BB * XS_STRIDE;      // 2 * XS_STRIDE
        float* dotS = ws + 2 * XS_STRIDE;       // 128
        float* mS   = dotS + 128;               // 2
        float* iS   = mS + 2;                   // 2

        const float* Wl[4] = {w0, w1, w2, w3};
        const float* Bl[4] = {b0, b1, b2, b3};
        const float* Gl[4] = {g0, g1, g2, g3};
        const float* El[4] = {e0, e1, e2, e3};

        const int o0 = bid * 2;

        for (int l = 0; l < 4; l++) {
            if (l == 0) {
                const float4* c4p = (const float4*)ocorr;
                const float4* l4p = (const float4*)l3;
                for (int i = tid; i < BB * 64; i += THREADS) {
                    int n = i >> 6, c4 = i & 63;
                    float4 v = (c4 < 32) ? __ldcg(c4p + n * 32 + c4)
                                         : __ldcg(l4p + n * 32 + (c4 - 32));
                    *(float4*)&xs[n * XS_STRIDE + c4 * 4] = v;
                }
            } else {
                const float4* src = (const float4*)&g_act[(l + 1) & 1][0];
                for (int i = tid; i < BB * 64; i += THREADS) {
                    int n = i >> 6, c4 = i & 63;
                    *(float4*)&xs[n * XS_STRIDE + c4 * 4] = __ldcg(src + i);
                }
            }
            if (tid < 2 * HH) {
                int oo = tid >> 8, k = tid & 255;
                ws[oo * XS_STRIDE + k] = Wl[l][(size_t)(o0 + oo) * HH + k];
            }
            __syncthreads();

            const int sub  = tid & 7;
            const int outi = tid >> 3;
            const int n    = outi >> 1;
            const int oc   = outi & 1;
            {
                const float* xr = &xs[n * XS_STRIDE + sub * 4];
                const float* wr = &ws[oc * XS_STRIDE + sub * 4];
                float p = 0.0f;
                #pragma unroll
                for (int t = 0; t < 8; t++) {
                    float4 xv = *(const float4*)(xr + t * 32);
                    float4 wv = *(const float4*)(wr + t * 32);
                    p = fmaf(xv.x, wv.x, p);
                    p = fmaf(xv.y, wv.y, p);
                    p = fmaf(xv.z, wv.z, p);
                    p = fmaf(xv.w, wv.w, p);
                }
                p += __shfl_down_sync(0xffffffffu, p, 4, 8);
                p += __shfl_down_sync(0xffffffffu, p, 2, 8);
                p += __shfl_down_sync(0xffffffffu, p, 1, 8);
                if (sub == 0) dotS[outi] = p + Bl[l][o0 + oc];
            }
            __syncthreads();

            if (tid < 64) {
                int oc2 = tid >> 5;
                int ll  = tid & 31;
                float a = dotS[ll * 2 + oc2];
                float c = dotS[(ll + 32) * 2 + oc2];
                float s = a + c, q = a * a + c * c;
                #pragma unroll
                for (int off = 16; off; off >>= 1) {
                    s += __shfl_down_sync(0xffffffffu, s, off);
                    q += __shfl_down_sync(0xffffffffu, q, off);
                }
                if (ll == 0) {
                    float m = s * (1.0f / 64.0f);
                    float v = q * (1.0f / 64.0f) - m * m;
                    mS[oc2] = m;
                    iS[oc2] = rsqrtf(v + 1e-5f);
                }
            }
            __syncthreads();

            if (tid < 128) {
                int nn = tid >> 1, occ = tid & 1;
                int o  = o0 + occ;
                float d = dotS[tid];
                float h = Gl[l][o] * (d - mS[occ]) * iS[occ] + El[l][o];
                g_act[l & 1][nn * HH + o] = fmaxf(h, 0.0f);
            }

            grid_barrier(1 + l);
        }
    }

    // ------------------------------------------------------------------
    // Final FC (block 0)
    // ------------------------------------------------------------------
    if (bid == 0) {
        const int n   = tid >> 4;
        const int sub = tid & 15;
        const float* hr = &g_act[1][n * HH + sub * 16];
        float p = 0.0f;
        #pragma unroll
        for (int t = 0; t < 16; t++)
            p = fmaf(__ldcg(hr + t), w4[sub * 16 + t], p);
        p += __shfl_down_sync(0xffffffffu, p, 8, 16);
        p += __shfl_down_sync(0xffffffffu, p, 4, 16);
        p += __shfl_down_sync(0xffffffffu, p, 2, 16);
        p += __shfl_down_sync(0xffffffffu, p, 1, 16);
        if (sub == 0) tc[n] = p + b4[0];
    }
}

// ---------------------------------------------------------------------------
extern "C" void kernel_launch(void* const* d_in, const int* in_sizes, int n_in,
                              void* d_out, int out_size)
{
    const float* xyz  = (const float*)d_in[0];
    const float* pts  = (const float*)d_in[1];
    const float* l3   = (const float*)d_in[2];
    const float* temp = (const float*)d_in[3];
    const float* w0   = (const float*)d_in[4];
    const float* b0   = (const float*)d_in[5];
    const float* g0   = (const float*)d_in[6];
    const float* e0   = (const float*)d_in[7];
    const float* w1   = (const float*)d_in[8];
    const float* b1   = (const float*)d_in[9];
    const float* g1   = (const float*)d_in[10];
    const float* e1   = (const float*)d_in[11];
    const float* w2   = (const float*)d_in[12];
    const float* b2   = (const float*)d_in[13];
    const float* g2   = (const float*)d_in[14];
    const float* e2   = (const float*)d_in[15];
    const float* w3   = (const float*)d_in[16];
    const float* b3   = (const float*)d_in[17];
    const float* g3   = (const float*)d_in[18];
    const float* e3   = (const float*)d_in[19];
    const float* w4   = (const float*)d_in[20];
    const float* b4   = (const float*)d_in[21];

    float* out   = (float*)d_out;
    float* tc    = out;
    float* tsys  = out + 64;
    float* opts  = out + 128;
    float* ocorr = out + 128 + (size_t)BB * CC * NN;

    cudaFuncSetAttribute(mega_kernel, cudaFuncAttributeMaxDynamicSharedMemorySize,
                         SMEM_BYTES);

    mega_kernel<<<GRIDN, THREADS, SMEM_BYTES>>>(
        xyz, pts, l3, temp,
        w0, b0, g0, e0,
        w1, b1, g1, e1,
        w2, b2, g2, e2,
        w3, b3, g3, e3,
        w4, b4,
        tc, tsys, opts, ocorr);

    (void)in_sizes; (void)n_in; (void)out_size;
}